// round 17
// baseline (speedup 1.0000x reference)
#include <cuda_runtime.h>
#include <cuda_fp16.h>
#include <math.h>
#include <stdint.h>

#define T_STEPS 160
#define BATCH   640
#define FDIM    40
#define HDIM    768
#define PJDIM   256
#define NBLK    120
#define NTHR    512

#define NCH0    5      // gates L0: K=296 padded to 320, chunks of 64
#define NCH12   8      // gates L1/2: K=512
#define NCHP    12     // proj: K=768
#define K0REAL  296

// ---------------- device globals ----------------------------------------------
__device__ float  g_c[3][HDIM * BATCH];     // fp32 cell, permuted [gc*640+row]
__device__ __half g_m[3][HDIM * BATCH];     // fp16 m, permuted [gc*640+row]
__device__ __half g_hh[3][BATCH * PJDIM];   // fp16 h, row-major
__device__ float  g_h[3][BATCH * PJDIM];    // fp32 h (final norm)
__device__ unsigned g_bar_count;
__device__ unsigned g_bar_gen;

// Pre-swizzled fp16 weights, gmem order == smem order (paired-k LDS.128 layout).
__device__ uint32_t g_W0pre[12 * NCH0  * 8192];
__device__ uint32_t g_W1pre[12 * NCH12 * 8192];
__device__ uint32_t g_W2pre[12 * NCH12 * 8192];
__device__ uint32_t g_Ppre [3 * 4 * NCHP * 2048];

__device__ __forceinline__ float sig_fast(float x) {
    float e = __expf(-x);
    float r; asm("rcp.approx.f32 %0, %1;" : "=f"(r) : "f"(1.0f + e));
    return r;
}
__device__ __forceinline__ float tanh_fast(float x) {
    float e = __expf(-2.0f * x);
    float r; asm("rcp.approx.f32 %0, %1;" : "=f"(r) : "f"(1.0f + e));
    return 2.0f * r - 1.0f;
}

__device__ __forceinline__ uint32_t f2h2(float a, float b) {
    __half2 h = __floats2half2_rn(a, b);
    return *(uint32_t*)&h;
}

__device__ __forceinline__ void mma_f16(float& c0, float& c1, float& c2, float& c3,
                                        uint32_t a0, uint32_t a1, uint32_t a2, uint32_t a3,
                                        uint32_t b0, uint32_t b1) {
    asm("mma.sync.aligned.m16n8k16.row.col.f32.f16.f16.f32 "
        "{%0,%1,%2,%3},{%4,%5,%6,%7},{%8,%9},{%0,%1,%2,%3};"
        : "+f"(c0), "+f"(c1), "+f"(c2), "+f"(c3)
        : "r"(a0), "r"(a1), "r"(a2), "r"(a3), "r"(b0), "r"(b1));
}

__device__ __forceinline__ void cp16(uint32_t dst, const void* src) {
    asm volatile("cp.async.cg.shared.global [%0], [%1], 16;" :: "r"(dst), "l"(src));
}
#define CP_COMMIT() asm volatile("cp.async.commit_group;")
#define CP_WAIT0()  asm volatile("cp.async.wait_group 0;" ::: "memory")

__device__ __forceinline__ void grid_barrier() {
    __syncthreads();
    if (threadIdx.x == 0) {
        __threadfence();
        unsigned gen = *(volatile unsigned*)&g_bar_gen;
        if (atomicAdd(&g_bar_count, 1u) == NBLK - 1) {
            g_bar_count = 0;
            __threadfence();
            atomicAdd(&g_bar_gen, 1u);
        } else {
            while (*(volatile unsigned*)&g_bar_gen == gen) { __nanosleep(64); }
        }
        __threadfence();
    }
    __syncthreads();
}

// ---------------- weight precompute (identical layout to R14-16) ----------------
__device__ void prep_w(uint32_t* dst, const float* W, long idx, int NCH, int K) {
    int nt = (int)(idx / ((long)NCH * 8192));
    int r  = (int)(idx % ((long)NCH * 8192));
    int ch = r / 8192, g = r % 8192;
    int u = g >> 2, w4 = g & 3;
    int sp = u >> 10, col = (u >> 2) & 255, qx = u & 3;
    int q = qx ^ ((col >> 1) & 3);
    int k = ch * 64 + (sp * 2 + (w4 >> 1)) * 16 + 2 * (q + 4 * (w4 & 1));
    int gate = col & 3;
    int wcol = gate * HDIM + nt * 64 + (col >> 2);
    float lo = (k     < K) ? W[(size_t)k * (4 * HDIM) + wcol] : 0.0f;
    float hf = (k + 1 < K) ? W[(size_t)(k + 1) * (4 * HDIM) + wcol] : 0.0f;
    dst[idx] = f2h2(lo, hf);
}

__global__ void precompute_weights(const float* __restrict__ W0, const float* __restrict__ W1,
                                   const float* __restrict__ W2, const float* __restrict__ P0,
                                   const float* __restrict__ P1, const float* __restrict__ P2)
{
    long idx = (long)blockIdx.x * 256 + threadIdx.x;
    const long NW0  = 12L * NCH0  * 8192;
    const long NW12 = 12L * NCH12 * 8192;
    if (idx < NW0)  { prep_w(g_W0pre, W0, idx, NCH0, K0REAL); return; }
    idx -= NW0;
    if (idx < NW12) { prep_w(g_W1pre, W1, idx, NCH12, 512); return; }
    idx -= NW12;
    if (idx < NW12) { prep_w(g_W2pre, W2, idx, NCH12, 512); return; }
    idx -= NW12;
    if (idx < 3L * 4 * NCHP * 2048) {
        long save = idx;
        int layer = (int)(idx / (4 * NCHP * 2048));
        int r  = (int)(idx % (4 * NCHP * 2048));
        int nt4 = r / (NCHP * 2048);
        int r2  = r % (NCHP * 2048);
        int ch  = r2 / 2048, g = r2 % 2048;
        int u = g >> 2, w4 = g & 3;
        int sp = u >> 8, col = (u >> 2) & 63, qx = u & 3;
        int q = qx ^ ((col >> 1) & 3);
        int k = ch * 64 + (sp * 2 + (w4 >> 1)) * 16 + 2 * (q + 4 * (w4 & 1));
        int n = nt4 * 64 + col;
        const float* P = (layer == 0) ? P0 : (layer == 1) ? P1 : P2;
        g_Ppre[save] = f2h2(P[k * PJDIM + n], P[(k + 1) * PJDIM + n]);
    }
}

// ---------------- gates: 64x256 tile, 16 warps (32x32), paired-chunk sync -------
// smem words: A bufs 4x2048 at [0,8192), W bufs 4x8192 at [8192, 40960)
template <int XK, int NCH>
__device__ void gates_tile(const float* __restrict__ xA,
                           const __half* __restrict__ h1,
                           const __half* __restrict__ h2,
                           const uint32_t* __restrict__ Wt,
                           const float* __restrict__ bias,
                           float* __restrict__ cbuf, __half* __restrict__ mbuf,
                           uint32_t* __restrict__ sm, uint32_t sb)
{
    const int tid = threadIdx.x, lane = tid & 31, wid = tid >> 5;
    const int bid = blockIdx.x;
    const int m0  = (bid % 10) * 64;
    const int nt0 = bid / 10;
    const int wm = wid >> 3, wn = wid & 7;          // 2 x 8 warps, tile 32x32
    const int grp = lane >> 2, q = lane & 3;
    const int qx4 = ((lane & 3) ^ ((lane >> 3) & 3)) * 4;
    const int row = tid >> 3, aj = tid & 7;          // A fill: 1 ld8/thread
    const int xs  = (row >> 1) & 3;

    float acc[2][4][4];
#pragma unroll
    for (int mt = 0; mt < 2; mt++)
#pragma unroll
        for (int nt = 0; nt < 4; nt++)
#pragma unroll
            for (int r = 0; r < 4; r++) acc[mt][nt][r] = 0.0f;

    auto ld8 = [&](int kg) -> uint4 {
        uint4 v;
        if (XK == 40) {
            if (kg < 40) {
                float4 f0 = __ldg((const float4*)&xA[(m0 + row) * 40 + kg]);
                float4 f1 = __ldg((const float4*)&xA[(m0 + row) * 40 + kg + 4]);
                v.x = f2h2(f0.x, f0.y); v.y = f2h2(f0.z, f0.w);
                v.z = f2h2(f1.x, f1.y); v.w = f2h2(f1.z, f1.w);
            } else if (kg < 296) {
                v = __ldcg((const uint4*)&h2[(m0 + row) * PJDIM + kg - 40]);
            } else {
                v = make_uint4(0u, 0u, 0u, 0u);
            }
        } else {
            if (kg < 256) v = __ldcg((const uint4*)&h1[(m0 + row) * PJDIM + kg]);
            else          v = __ldcg((const uint4*)&h2[(m0 + row) * PJDIM + kg - 256]);
        }
        return v;
    };
    auto stA1 = [&](int ch, const uint4& hv) {
        int buf = ch & 3;
        int sp = aj >> 2, ajj = aj & 3;
        uint32_t* d = sm + buf * 2048 + sp * 1024 + row * 16 + (ajj >> 1) * 2 + (ajj & 1);
        d[(0 ^ xs) << 2] = hv.x; d[(1 ^ xs) << 2] = hv.y;
        d[(2 ^ xs) << 2] = hv.z; d[(3 ^ xs) << 2] = hv.w;
    };
    auto ldW1 = [&](int ch) {
        int buf = ch & 3;
        const uint32_t* src = Wt + (size_t)ch * 8192 + tid * 4;
        uint32_t dst = sb + (8192 + buf * 8192 + tid * 4) * 4;
#pragma unroll
        for (int e = 0; e < 4; e++) cp16(dst + e * 8192, src + e * 2048);
    };
    auto mma_chunk = [&](int ch) {
        int buf = ch & 3;
        const uint32_t* bA = sm + buf * 2048;
        const uint32_t* bW = sm + 8192 + buf * 8192;
#pragma unroll
        for (int sp = 0; sp < 2; sp++) {
            uint4 A0[2], A1[2];
#pragma unroll
            for (int mt = 0; mt < 2; mt++) {
                int r0 = wm * 32 + mt * 16 + grp;
                A0[mt] = *(const uint4*)&bA[sp * 1024 + r0 * 16 + qx4];
                A1[mt] = *(const uint4*)&bA[sp * 1024 + (r0 + 8) * 16 + qx4];
            }
#pragma unroll
            for (int nt = 0; nt < 4; nt++) {
                int col = wn * 32 + nt * 8 + grp;
                uint4 B = *(const uint4*)&bW[sp * 4096 + col * 16 + qx4];
#pragma unroll
                for (int mt = 0; mt < 2; mt++) {
                    mma_f16(acc[mt][nt][0], acc[mt][nt][1], acc[mt][nt][2], acc[mt][nt][3],
                            A0[mt].x, A1[mt].x, A0[mt].y, A1[mt].y, B.x, B.y);
                    mma_f16(acc[mt][nt][0], acc[mt][nt][1], acc[mt][nt][2], acc[mt][nt][3],
                            A0[mt].z, A1[mt].z, A0[mt].w, A1[mt].w, B.z, B.w);
                }
            }
        }
    };

    // prologue: pair (0,1) as one cp group
    {
        uint4 a0 = ld8(0 * 64 + aj * 8);
        uint4 a1 = ld8(1 * 64 + aj * 8);
        stA1(0, a0); stA1(1, a1);
        ldW1(0); ldW1(1); CP_COMMIT();
    }

    int ch = 0;
    for (; ch + 1 < NCH; ch += 2) {
        int n0 = ch + 2, n1 = ch + 3;
        uint4 a0, a1;
        if (n0 < NCH) a0 = ld8(n0 * 64 + aj * 8);    // LDG overlaps cp wait
        if (n1 < NCH) a1 = ld8(n1 * 64 + aj * 8);
        CP_WAIT0();
        __syncthreads();
        if (n0 < NCH) { stA1(n0, a0); ldW1(n0); }
        if (n1 < NCH) { stA1(n1, a1); ldW1(n1); }
        if (n0 < NCH) CP_COMMIT();
        mma_chunk(ch);
        mma_chunk(ch + 1);
    }
    if (ch < NCH) {                      // odd tail (NCH0 = 5)
        CP_WAIT0();
        __syncthreads();
        mma_chunk(ch);
    }

    // Epilogue: lane pair (lane^1) assembles (i,j,f,o) per cell column.
    const int gc0 = nt0 * 64;
    const int p = lane & 1;
#pragma unroll
    for (int nt = 0; nt < 4; nt++) {
        int cc = wn * 8 + 2 * nt + (q >> 1);
        int gc = gc0 + cc;
        float bi = __ldg(&bias[gc]);
        float bj = __ldg(&bias[gc + HDIM]);
        float bf = __ldg(&bias[gc + 2 * HDIM]);
        float bo = __ldg(&bias[gc + 3 * HDIM]);
#pragma unroll
        for (int mt = 0; mt < 2; mt++) {
            float c0 = acc[mt][nt][0], c1 = acc[mt][nt][1];
            float c2 = acc[mt][nt][2], c3 = acc[mt][nt][3];
            float v = __shfl_xor_sync(0xffffffffu, p ? c0 : c2, 1);
            float w = __shfl_xor_sync(0xffffffffu, p ? c1 : c3, 1);
            float zi, zj, zf, zo;
            if (p == 0) { zi = c0; zj = c1; zf = v;  zo = w;  }
            else        { zi = v;  zj = w;  zf = c2; zo = c3; }
            int rowE = m0 + wm * 32 + mt * 16 + grp + (p ? 8 : 0);
            zi += bi; zj += bj; zf += bf; zo += bo;
            float cold = cbuf[gc * BATCH + rowE];
            float cn = sig_fast(zf + 1.0f) * cold + sig_fast(zi) * tanh_fast(zj);
            float mm = sig_fast(zo) * tanh_fast(cn);
            cbuf[gc * BATCH + rowE] = cn;
            mbuf[gc * BATCH + rowE] = __float2half(mm);
        }
    }
    __syncthreads();   // protect smem bufs from next tile call's prologue
}

// ---------------- projection: 64x64 tile, 16 warps (16x16), paired-chunk sync ---
// smem words: A bufs 4x2048 at [0,8192), W bufs 4x2048 at [8192,16384)
__device__ void proj_mma(const __half* __restrict__ mperm,
                         const uint32_t* __restrict__ Pblk,
                         float* __restrict__ hL, __half* __restrict__ hhL,
                         int m0, int nt4,
                         uint32_t* __restrict__ sm, uint32_t sb)
{
    const int tid = threadIdx.x, lane = tid & 31, wid = tid >> 5;
    const int wm = wid >> 2, wn = wid & 3;
    const int grp = lane >> 2, q = lane & 3;
    const int qx4 = ((lane & 3) ^ ((lane >> 3) & 3)) * 4;
    const int klocal = tid >> 3;           // 0..63
    const int row8 = (tid & 7) * 8;

    float acc[2][4];
#pragma unroll
    for (int nt = 0; nt < 2; nt++)
#pragma unroll
        for (int r = 0; r < 4; r++) acc[nt][r] = 0.0f;

    auto ldA = [&](int ch) -> uint4 {
        return __ldcg((const uint4*)&mperm[(ch * 64 + klocal) * BATCH + m0 + row8]);
    };
    auto stA1 = [&](int ch, const uint4& hv) {   // R13 layout per buf
        int buf = ch & 3;
        int kw = klocal >> 1, hsel = klocal & 1;
        int s = kw >> 3, kw8 = kw & 7;
        int pos = (kw8 & 3) * 2 + (kw8 >> 2);
        __half hs[8];
        *(uint32_t*)&hs[0] = hv.x; *(uint32_t*)&hs[2] = hv.y;
        *(uint32_t*)&hs[4] = hv.z; *(uint32_t*)&hs[6] = hv.w;
#pragma unroll
        for (int e = 0; e < 8; e++) {
            int rw = row8 + e;
            int xr = ((rw >> 3) & 3) << 1;
            __half* hp = (__half*)(sm + buf * 2048 + s * 512 + rw * 8 + (pos ^ xr));
            hp[hsel] = hs[e];
        }
    };
    auto ldW1 = [&](int ch) {
        int buf = ch & 3;
        cp16(sb + (8192 + buf * 2048 + tid * 4) * 4, Pblk + (size_t)ch * 2048 + tid * 4);
    };
    auto mma_chunk = [&](int ch) {
        int buf = ch & 3;
        const uint32_t* bA = sm + buf * 2048;
        const uint32_t* bW = sm + 8192 + buf * 2048;
#pragma unroll
        for (int sp = 0; sp < 2; sp++) {
            uint4 Bn[2];
#pragma unroll
            for (int nt = 0; nt < 2; nt++) {
                int col = wn * 16 + nt * 8 + grp;
                Bn[nt] = *(const uint4*)&bW[sp * 1024 + col * 16 + qx4];
            }
#pragma unroll
            for (int s01 = 0; s01 < 2; s01++) {
                int s = sp * 2 + s01;
                int r0 = wm * 16 + grp;
                int r1 = r0 + 8;
                int x0 = ((r0 >> 3) & 3) << 1;
                int x1 = ((r1 >> 3) & 3) << 1;
                uint2 a02 = *(const uint2*)&bA[s * 512 + r0 * 8 + ((q * 2) ^ x0)];
                uint2 a13 = *(const uint2*)&bA[s * 512 + r1 * 8 + ((q * 2) ^ x1)];
#pragma unroll
                for (int nt = 0; nt < 2; nt++) {
                    uint32_t b0 = s01 ? Bn[nt].z : Bn[nt].x;
                    uint32_t b1 = s01 ? Bn[nt].w : Bn[nt].y;
                    mma_f16(acc[nt][0], acc[nt][1], acc[nt][2], acc[nt][3],
                            a02.x, a13.x, a02.y, a13.y, b0, b1);
                }
            }
        }
    };

    {
        uint4 a0 = ldA(0), a1 = ldA(1);
        stA1(0, a0); stA1(1, a1);
        ldW1(0); ldW1(1); CP_COMMIT();
    }

    for (int ch = 0; ch < NCHP; ch += 2) {       // NCHP = 12 (even)
        int n0 = ch + 2, n1 = ch + 3;
        uint4 a0, a1;
        if (n0 < NCHP) a0 = ldA(n0);
        if (n1 < NCHP) a1 = ldA(n1);
        CP_WAIT0();
        __syncthreads();
        if (n0 < NCHP) { stA1(n0, a0); ldW1(n0); }
        if (n1 < NCHP) { stA1(n1, a1); ldW1(n1); }
        if (n0 < NCHP) CP_COMMIT();
        mma_chunk(ch);
        mma_chunk(ch + 1);
    }

#pragma unroll
    for (int nt = 0; nt < 2; nt++) {
        int rw = m0 + wm * 16 + grp;
        int col = nt4 * 64 + wn * 16 + nt * 8 + 2 * q;
        *(float2*)&hL[rw * PJDIM + col] = make_float2(acc[nt][0], acc[nt][1]);
        *(float2*)&hL[(rw + 8) * PJDIM + col] = make_float2(acc[nt][2], acc[nt][3]);
        *(uint32_t*)&hhL[rw * PJDIM + col] = f2h2(acc[nt][0], acc[nt][1]);
        *(uint32_t*)&hhL[(rw + 8) * PJDIM + col] = f2h2(acc[nt][2], acc[nt][3]);
    }
    __syncthreads();   // protect smem bufs from next tile call's prologue
}

// ---------------- persistent driver ----------------------------------------------
__global__ void __launch_bounds__(NTHR, 1)
lstm_persistent(const float* __restrict__ x,
                const float* __restrict__ b0, const float* __restrict__ b1,
                const float* __restrict__ b2, float* __restrict__ out)
{
    extern __shared__ uint32_t dynsmem[];   // 40960 words = 160KB
    __shared__ float red[16];
    uint32_t* sm = dynsmem;
    uint32_t sb = (uint32_t)__cvta_generic_to_shared(dynsmem);

    const int bid = blockIdx.x;
    const int tid = threadIdx.x;

    for (int i = bid * NTHR + tid; i < 3 * HDIM * BATCH; i += NBLK * NTHR)
        ((float*)g_c)[i] = 0.0f;
    for (int i = bid * NTHR + tid; i < 3 * BATCH * PJDIM / 2; i += NBLK * NTHR)
        ((uint32_t*)g_hh)[i] = 0u;
    for (int i = bid * NTHR + tid; i < 3 * BATCH * PJDIM; i += NBLK * NTHR)
        ((float*)g_h)[i] = 0.0f;
    grid_barrier();

    const int g_nt = bid / 10;
    const uint32_t* W0t = g_W0pre + (size_t)g_nt * NCH0  * 8192;
    const uint32_t* W1t = g_W1pre + (size_t)g_nt * NCH12 * 8192;
    const uint32_t* W2t = g_W2pre + (size_t)g_nt * NCH12 * 8192;

    const int p_layer = bid / 40, p_rem = bid % 40;
    const int p_m0 = (p_rem % 10) * 64, p_nt4 = p_rem / 10;
    const uint32_t* Pblk = g_Ppre + ((size_t)p_layer * 4 + p_nt4) * NCHP * 2048;

    for (int s = 0; s < T_STEPS + 2; s++) {
        if (s < T_STEPS)
            gates_tile<40, NCH0>(x + (size_t)s * BATCH * FDIM, (const __half*)nullptr,
                                 g_hh[0], W0t, b0, g_c[0], g_m[0], sm, sb);
        if (s >= 1 && s - 1 < T_STEPS)
            gates_tile<256, NCH12>(nullptr, g_hh[0], g_hh[1], W1t, b1,
                                   g_c[1], g_m[1], sm, sb);
        if (s >= 2 && s - 2 < T_STEPS)
            gates_tile<256, NCH12>(nullptr, g_hh[1], g_hh[2], W2t, b2,
                                   g_c[2], g_m[2], sm, sb);
        grid_barrier();

        if (s - p_layer >= 0 && s - p_layer < T_STEPS)
            proj_mma(g_m[p_layer], Pblk, g_h[p_layer], g_hh[p_layer],
                     p_m0, p_nt4, sm, sb);
        grid_barrier();
    }

    // L2 normalize: 512 threads handle 2 batches/block-pass (warps 0-7 / 8-15).
    const int half = tid >> 8;        // 0 or 1
    const int t    = tid & 255;
    for (int bb = bid; bb < BATCH / 2; bb += NBLK) {
        int b = bb * 2 + half;
        float v = __ldcg(&g_h[2][b * PJDIM + t]);
        float sm2 = v * v;
#pragma unroll
        for (int o = 16; o > 0; o >>= 1) sm2 += __shfl_xor_sync(0xffffffffu, sm2, o);
        if ((tid & 31) == 0) red[tid >> 5] = sm2;
        __syncthreads();
        float tot = 0.0f;
#pragma unroll
        for (int wv = 0; wv < 8; wv++) tot += red[half * 8 + wv];
        out[b * PJDIM + t] = v * rsqrtf(fmaxf(tot, 1e-12f));
        __syncthreads();
    }
}

extern "C" void kernel_launch(void* const* d_in, const int* in_sizes, int n_in,
                              void* d_out, int out_size)
{
    const float* x  = (const float*)d_in[0];
    const float* W0 = (const float*)d_in[1];
    const float* b0 = (const float*)d_in[2];
    const float* P0 = (const float*)d_in[3];
    const float* W1 = (const float*)d_in[4];
    const float* b1 = (const float*)d_in[5];
    const float* P1 = (const float*)d_in[6];
    const float* W2 = (const float*)d_in[7];
    const float* b2 = (const float*)d_in[8];
    const float* P2 = (const float*)d_in[9];
    float* out = (float*)d_out;
    (void)in_sizes; (void)n_in; (void)out_size;

    static int attr_done = 0;
    if (!attr_done) {
        cudaFuncSetAttribute(lstm_persistent,
                             cudaFuncAttributeMaxDynamicSharedMemorySize, 163840);
        attr_done = 1;
    }

    precompute_weights<<<9216, 256>>>(W0, W1, W2, P0, P1, P2);
    lstm_persistent<<<NBLK, NTHR, 163840>>>(x, b0, b1, b2, out);
}